// round 14
// baseline (speedup 1.0000x reference)
#include <cuda_runtime.h>
#include <cstdint>
#include <cstddef>

// ---------------------------------------------------------------------------
// Scratch: x_proj buffer [B*T, H] = [262144, 256] fp32 = 256 MiB
// ---------------------------------------------------------------------------
__device__ float g_xproj[64u * 4096u * 256u];

// 2 * log2(e)
#define L2E2 2.8853900817779268f

// ---------------------------------------------------------------------------
// tanh on a PRE-SCALED argument z2 = 2*log2(e)*z :  tanh(z) = 1 - 2/(2^z2+1)
// ---------------------------------------------------------------------------
__device__ __forceinline__ float tanh_pre(float z2) {
    float e;
    asm("ex2.approx.f32 %0, %1;" : "=f"(e) : "f"(z2));
    float r;
    asm("rcp.approx.f32 %0, %1;" : "=f"(r) : "f"(e + 1.0f));
    return fmaf(-2.0f, r, 1.0f);
}

// ---------------------------------------------------------------------------
// Packed f32x2 helpers
// ---------------------------------------------------------------------------
__device__ __forceinline__ uint64_t ffma2(uint64_t a, uint64_t b, uint64_t c) {
    uint64_t d;
    asm("fma.rn.f32x2 %0, %1, %2, %3;" : "=l"(d) : "l"(a), "l"(b), "l"(c));
    return d;
}
__device__ __forceinline__ uint64_t fadd2(uint64_t a, uint64_t b) {
    uint64_t d;
    asm("add.rn.f32x2 %0, %1, %2;" : "=l"(d) : "l"(a), "l"(b));
    return d;
}
__device__ __forceinline__ float f2sum(uint64_t v) {
    float lo, hi;
    asm("mov.b64 {%0, %1}, %2;" : "=f"(lo), "=f"(hi) : "l"(v));
    return lo + hi;
}
__device__ __forceinline__ uint64_t pack2(float lo, float hi) {
    uint64_t d;
    asm("mov.b64 %0, {%1, %2};" : "=l"(d) : "f"(lo), "f"(hi));
    return d;
}
__device__ __forceinline__ void unpack2(uint64_t v, float& lo, float& hi) {
    asm("mov.b64 {%0, %1}, %2;" : "=f"(lo), "=f"(hi) : "l"(v));
}

__device__ __forceinline__ uint32_t smem_u32(const void* p) {
    uint32_t a;
    asm("{ .reg .u64 t; cvta.to.shared.u64 t, %1; cvt.u32.u64 %0, t; }"
        : "=r"(a) : "l"(p));
    return a;
}
__device__ __forceinline__ uint32_t mapa_rank(uint32_t laddr, uint32_t rank) {
    uint32_t raddr;
    asm("mapa.shared::cluster.u32 %0, %1, %2;" : "=r"(raddr) : "r"(laddr), "r"(rank));
    return raddr;
}
// Async 8-byte store completing tx on the given (cluster-addr) mbarrier.
__device__ __forceinline__ void st_async_b64(uint32_t raddr, uint64_t v, uint32_t rmbar) {
    asm volatile(
        "st.async.shared::cluster.mbarrier::complete_tx::bytes.b64 [%0], %1, [%2];"
        :: "r"(raddr), "l"(v), "r"(rmbar) : "memory");
}
__device__ __forceinline__ void mbar_init(uint32_t addr, uint32_t cnt) {
    asm volatile("mbarrier.init.shared.b64 [%0], %1;" :: "r"(addr), "r"(cnt) : "memory");
}
__device__ __forceinline__ void mbar_arrive_expect_tx(uint32_t addr, uint32_t tx) {
    asm volatile("mbarrier.arrive.expect_tx.shared.b64 _, [%0], %1;"
                 :: "r"(addr), "r"(tx) : "memory");
}
__device__ __forceinline__ void mbar_wait_parity(uint32_t addr, uint32_t parity) {
    uint32_t done;
    asm volatile(
        "{\n\t.reg .pred p;\n\t"
        "mbarrier.try_wait.parity.acquire.cta.shared::cta.b64 p, [%1], %2;\n\t"
        "selp.b32 %0, 1, 0, p;\n\t}"
        : "=r"(done) : "r"(addr), "r"(parity) : "memory");
    if (!done) {
        asm volatile(
            "{\n\t.reg .pred P1;\n\t"
            "WL_%=:\n\t"
            "mbarrier.try_wait.parity.acquire.cta.shared::cta.b64 P1, [%0], %1, 0x989680;\n\t"
            "@P1 bra.uni WD_%=;\n\t"
            "bra.uni WL_%=;\n\t"
            "WD_%=:\n\t}"
            :: "r"(addr), "r"(parity) : "memory");
    }
}

#define CLUSTER_SYNC_() do { \
    asm volatile("barrier.cluster.arrive.aligned;" ::: "memory"); \
    asm volatile("barrier.cluster.wait.aligned;" ::: "memory"); } while (0)

// ---------------------------------------------------------------------------
// Kernel 1: x_proj = x @ W_in^T + b_in  (128x128 tile, packed f32x2 FMA)
// ---------------------------------------------------------------------------
#define XP_BM 128
#define XP_BN 128
#define XP_BK 16

__global__ __launch_bounds__(256) void xproj_kernel(
    const float* __restrict__ x, const float* __restrict__ Win,
    const float* __restrict__ bin, float* __restrict__ out,
    int M, int K, int N)
{
    __shared__ float As[XP_BK][XP_BM];
    __shared__ float Bs[XP_BK][XP_BN];

    const int tid = threadIdx.x;
    const int tx = tid & 15;
    const int ty = tid >> 4;
    const int n0 = blockIdx.x * XP_BN;
    const int m0 = blockIdx.y * XP_BM;

    const int lr = tid >> 1;
    const int lc = (tid & 1) * 8;

    uint64_t cc[8][4];
    #pragma unroll
    for (int i = 0; i < 8; i++)
        #pragma unroll
        for (int jj = 0; jj < 4; jj++) cc[i][jj] = 0ull;

    for (int k0 = 0; k0 < K; k0 += XP_BK) {
        float4 xa0 = *(const float4*)(x   + (size_t)(m0 + lr) * K + k0 + lc);
        float4 xa1 = *(const float4*)(x   + (size_t)(m0 + lr) * K + k0 + lc + 4);
        float4 wb0 = *(const float4*)(Win + (size_t)(n0 + lr) * K + k0 + lc);
        float4 wb1 = *(const float4*)(Win + (size_t)(n0 + lr) * K + k0 + lc + 4);
        As[lc + 0][lr] = xa0.x; As[lc + 1][lr] = xa0.y;
        As[lc + 2][lr] = xa0.z; As[lc + 3][lr] = xa0.w;
        As[lc + 4][lr] = xa1.x; As[lc + 5][lr] = xa1.y;
        As[lc + 6][lr] = xa1.z; As[lc + 7][lr] = xa1.w;
        Bs[lc + 0][lr] = wb0.x; Bs[lc + 1][lr] = wb0.y;
        Bs[lc + 2][lr] = wb0.z; Bs[lc + 3][lr] = wb0.w;
        Bs[lc + 4][lr] = wb1.x; Bs[lc + 5][lr] = wb1.y;
        Bs[lc + 6][lr] = wb1.z; Bs[lc + 7][lr] = wb1.w;
        __syncthreads();

        #pragma unroll
        for (int kk = 0; kk < XP_BK; kk++) {
            float4 a0 = *(const float4*)(&As[kk][ty * 8]);
            float4 a1 = *(const float4*)(&As[kk][ty * 8 + 4]);
            ulonglong2 b0 = *(const ulonglong2*)(&Bs[kk][tx * 8]);
            ulonglong2 b1 = *(const ulonglong2*)(&Bs[kk][tx * 8 + 4]);
            float av[8] = {a0.x, a0.y, a0.z, a0.w, a1.x, a1.y, a1.z, a1.w};
            uint64_t bp[4] = {b0.x, b0.y, b1.x, b1.y};
            #pragma unroll
            for (int mi = 0; mi < 8; mi++) {
                uint64_t ap = pack2(av[mi], av[mi]);
                #pragma unroll
                for (int ni = 0; ni < 4; ni++)
                    cc[mi][ni] = ffma2(ap, bp[ni], cc[mi][ni]);
            }
        }
        __syncthreads();
    }

    float bb[8];
    #pragma unroll
    for (int ni = 0; ni < 8; ni++) bb[ni] = __ldg(&bin[n0 + tx * 8 + ni]);

    #pragma unroll
    for (int mi = 0; mi < 8; mi++) {
        int row = m0 + ty * 8 + mi;
        float c[8];
        #pragma unroll
        for (int ni = 0; ni < 4; ni++) unpack2(cc[mi][ni], c[2 * ni], c[2 * ni + 1]);
        float4 o0 = make_float4(c[0] + bb[0], c[1] + bb[1], c[2] + bb[2], c[3] + bb[3]);
        float4 o1 = make_float4(c[4] + bb[4], c[5] + bb[5], c[6] + bb[6], c[7] + bb[7]);
        *(float4*)(out + (size_t)row * N + n0 + tx * 8)     = o0;
        *(float4*)(out + (size_t)row * N + n0 + tx * 8 + 4) = o1;
    }
}

// ---------------------------------------------------------------------------
// Kernel 2: LTC scan — R12 champion architecture, TWO BATCHES PER CLUSTER.
//   32 clusters x 2 CTAs; cluster c handles batches (2c, 2c+1) interleaved.
//   W is batch-independent -> the same 64 wd registers serve both batches.
//   Per inner iter: FMA_A -> send_A -> FMA_B -> send_B -> wait_A -> finish_A
//   -> wait_B -> finish_B -> one bar.  Batch A's DSMEM flight (~215 cyc) is
//   hidden under batch B's FMA phase (~290 cyc); only part of B's flight is
//   exposed.  K-SPLIT partial exchange exactly as R12 (FMA reads only
//   locally-written smem; finish redundant on both CTAs).
// ---------------------------------------------------------------------------
#define LTC_H 256

__global__ __launch_bounds__(256, 1) __cluster_dims__(2, 1, 1)
void ltc_scan_kernel(
    const float* __restrict__ xproj,
    const float* __restrict__ Wrec,
    const float* __restrict__ brec,
    const float* __restrict__ tau,
    const int*   __restrict__ nl_p,
    float* __restrict__ out, int T, int Btot)
{
    __shared__ __align__(16) float hbufA[2][LTC_H];
    __shared__ __align__(16) float hbufB[2][LTC_H];
    __shared__ __align__(16) float ppartA[2][LTC_H];
    __shared__ __align__(16) float ppartB[2][LTC_H];
    __shared__ __align__(16) unsigned long long mbar[4];  // A0,A1,B0,B1

    const int cl = blockIdx.x >> 1;          // cluster id
    const int bA = 2 * cl;
    const int bB = 2 * cl + 1;
    const bool hasB = (bB < Btot);

    uint32_t rank;
    asm("mov.u32 %0, %%cluster_ctarank;" : "=r"(rank));
    const uint32_t peer = rank ^ 1u;

    const int t_ = threadIdx.x;              // output index 0..255

    // --- W_rec[t][rank*128 .. +127] * 2log2e -> 64 packed f32x2 regs ------
    uint64_t wd[64];
    {
        const float4* wrow =
            (const float4*)(Wrec + (size_t)t_ * LTC_H + (rank << 7));
        #pragma unroll
        for (int i = 0; i < 32; i++) {
            float4 v = wrow[i];
            wd[2 * i]     = pack2(v.x * L2E2, v.y * L2E2);
            wd[2 * i + 1] = pack2(v.z * L2E2, v.w * L2E2);
        }
    }

    const float brec_j = brec[t_];
    const float scale_j = 0.1f / fminf(fmaxf(tau[t_], 0.1f), 5.0f);

    int NL = 2;
    if (nl_p) {
        int v = *nl_p;
        if (v >= 1 && v <= 64) NL = v;
    }

    const uint32_t mbA[2] = { smem_u32(&mbar[0]), smem_u32(&mbar[1]) };
    const uint32_t mbB[2] = { smem_u32(&mbar[2]), smem_u32(&mbar[3]) };
    if (t_ == 0) {
        mbar_init(mbA[0], 1); mbar_init(mbA[1], 1);
        mbar_init(mbB[0], 1); mbar_init(mbB[1], 1);
    }
    hbufA[0][t_] = 0.0f; hbufA[1][t_] = 0.0f;
    hbufB[0][t_] = 0.0f; hbufB[1][t_] = 0.0f;
    __syncthreads();
    CLUSTER_SYNC_();   // peer mbars + zeros visible before any st.async

    // remote (peer) targets; even lane sends the pair (t_, t_+1) as b64
    const uint32_t r_ppA[2] = {
        mapa_rank(smem_u32(&ppartA[0][t_ & ~1]), peer),
        mapa_rank(smem_u32(&ppartA[1][t_ & ~1]), peer)
    };
    const uint32_t r_ppB[2] = {
        mapa_rank(smem_u32(&ppartB[0][t_ & ~1]), peer),
        mapa_rank(smem_u32(&ppartB[1][t_ & ~1]), peer)
    };
    const uint32_t r_mbA[2] = { mapa_rank(mbA[0], peer), mapa_rank(mbA[1], peer) };
    const uint32_t r_mbB[2] = { mapa_rank(mbB[0], peer), mapa_rank(mbB[1], peer) };

    const float* xrowA = xproj + ((size_t)bA * T) * LTC_H + t_;
    const float* xrowB = xproj + ((size_t)(hasB ? bB : bA) * T) * LTC_H + t_;
    float xtA = __ldg(xrowA);
    float xtB = __ldg(xrowB);
    float hA = 0.0f, hB = 0.0f;
    const bool sender = !(t_ & 1);

    if (NL == 2) {
        for (int t = 0; t < T; t++) {
            const float base2A = (xtA + brec_j) * L2E2;
            const float base2B = (xtB + brec_j) * L2E2;
            if (t + 1 < T) {
                xtA = __ldg(xrowA + (size_t)(t + 1) * LTC_H);
                xtB = __ldg(xrowB + (size_t)(t + 1) * LTC_H);
            }
            const uint32_t par = (uint32_t)t & 1u;

            #pragma unroll
            for (int l = 0; l < 2; l++) {
                if (t_ == 0) {
                    mbar_arrive_expect_tx(mbA[l], LTC_H * 4u);
                    mbar_arrive_expect_tx(mbB[l], LTC_H * 4u);
                }

                // ---- batch A: partial + send ----
                const ulonglong2* hpA = (const ulonglong2*)(hbufA[l] + (rank << 7));
                uint64_t a0 = 0ull, a1 = 0ull, a2 = 0ull, a3 = 0ull;
                #pragma unroll
                for (int i = 0; i < 32; i += 2) {
                    ulonglong2 h0 = hpA[i];
                    ulonglong2 h1 = hpA[i + 1];
                    a0 = ffma2(wd[2 * i],     h0.x, a0);
                    a1 = ffma2(wd[2 * i + 1], h0.y, a1);
                    a2 = ffma2(wd[2 * i + 2], h1.x, a2);
                    a3 = ffma2(wd[2 * i + 3], h1.y, a3);
                }
                const float partA = f2sum(fadd2(fadd2(a0, a1), fadd2(a2, a3)));
                const float poA = __shfl_xor_sync(0xffffffffu, partA, 1);
                if (sender) st_async_b64(r_ppA[l], pack2(partA, poA), r_mbA[l]);

                // ---- batch B: partial + send (overlaps A's flight) ----
                const ulonglong2* hpB = (const ulonglong2*)(hbufB[l] + (rank << 7));
                uint64_t c0 = 0ull, c1 = 0ull, c2 = 0ull, c3 = 0ull;
                #pragma unroll
                for (int i = 0; i < 32; i += 2) {
                    ulonglong2 h0 = hpB[i];
                    ulonglong2 h1 = hpB[i + 1];
                    c0 = ffma2(wd[2 * i],     h0.x, c0);
                    c1 = ffma2(wd[2 * i + 1], h0.y, c1);
                    c2 = ffma2(wd[2 * i + 2], h1.x, c2);
                    c3 = ffma2(wd[2 * i + 3], h1.y, c3);
                }
                const float partB = f2sum(fadd2(fadd2(c0, c1), fadd2(c2, c3)));
                const float poB = __shfl_xor_sync(0xffffffffu, partB, 1);
                if (sender) st_async_b64(r_ppB[l], pack2(partB, poB), r_mbB[l]);

                // ---- finish A (its flight hid under B's FMA) ----
                mbar_wait_parity(mbA[l], par);
                const float actA = tanh_pre(base2A + partA + ppartA[l][t_]);
                hA = fmaf(scale_j, actA - hA, hA);
                hbufA[l ^ 1][t_] = hA;

                // ---- finish B ----
                mbar_wait_parity(mbB[l], par);
                const float actB = tanh_pre(base2B + partB + ppartB[l][t_]);
                hB = fmaf(scale_j, actB - hB, hB);
                hbufB[l ^ 1][t_] = hB;

                __syncthreads();
            }
        }
    } else {
        unsigned it = 0;
        uint32_t ph[2] = {0, 0};
        for (int t = 0; t < T; t++) {
            const float base2A = (xtA + brec_j) * L2E2;
            const float base2B = (xtB + brec_j) * L2E2;
            if (t + 1 < T) {
                xtA = __ldg(xrowA + (size_t)(t + 1) * LTC_H);
                xtB = __ldg(xrowB + (size_t)(t + 1) * LTC_H);
            }
            for (int l = 0; l < NL; l++) {
                const int slot = it & 1u;
                if (t_ == 0) {
                    mbar_arrive_expect_tx(mbA[slot], LTC_H * 4u);
                    mbar_arrive_expect_tx(mbB[slot], LTC_H * 4u);
                }

                const ulonglong2* hpA = (const ulonglong2*)(hbufA[slot] + (rank << 7));
                uint64_t a0 = 0ull, a1 = 0ull, a2 = 0ull, a3 = 0ull;
                #pragma unroll
                for (int i = 0; i < 32; i += 2) {
                    ulonglong2 h0 = hpA[i];
                    ulonglong2 h1 = hpA[i + 1];
                    a0 = ffma2(wd[2 * i],     h0.x, a0);
                    a1 = ffma2(wd[2 * i + 1], h0.y, a1);
                    a2 = ffma2(wd[2 * i + 2], h1.x, a2);
                    a3 = ffma2(wd[2 * i + 3], h1.y, a3);
                }
                const float partA = f2sum(fadd2(fadd2(a0, a1), fadd2(a2, a3)));
                const float poA = __shfl_xor_sync(0xffffffffu, partA, 1);
                if (sender) st_async_b64(r_ppA[slot], pack2(partA, poA), r_mbA[slot]);

                const ulonglong2* hpB = (const ulonglong2*)(hbufB[slot] + (rank << 7));
                uint64_t c0 = 0ull, c1 = 0ull, c2 = 0ull, c3 = 0ull;
                #pragma unroll
                for (int i = 0; i < 32; i += 2) {
                    ulonglong2 h0 = hpB[i];
                    ulonglong2 h1 = hpB[i + 1];
                    c0 = ffma2(wd[2 * i],     h0.x, c0);
                    c1 = ffma2(wd[2 * i + 1], h0.y, c1);
                    c2 = ffma2(wd[2 * i + 2], h1.x, c2);
                    c3 = ffma2(wd[2 * i + 3], h1.y, c3);
                }
                const float partB = f2sum(fadd2(fadd2(c0, c1), fadd2(c2, c3)));
                const float poB = __shfl_xor_sync(0xffffffffu, partB, 1);
                if (sender) st_async_b64(r_ppB[slot], pack2(partB, poB), r_mbB[slot]);

                mbar_wait_parity(mbA[slot], ph[slot]);
                const float actA = tanh_pre(base2A + partA + ppartA[slot][t_]);
                hA = fmaf(scale_j, actA - hA, hA);
                hbufA[slot ^ 1][t_] = hA;

                mbar_wait_parity(mbB[slot], ph[slot]);
                const float actB = tanh_pre(base2B + partB + ppartB[slot][t_]);
                hB = fmaf(scale_j, actB - hB, hB);
                hbufB[slot ^ 1][t_] = hB;

                ph[slot] ^= 1;
                __syncthreads();
                it++;
            }
        }
    }

    if (rank == 0) {
        out[(size_t)bA * LTC_H + t_] = hA;
        if (hasB) out[(size_t)bB * LTC_H + t_] = hB;
    }

    CLUSTER_SYNC_();   // don't exit while peer stores may target our smem
}

// ---------------------------------------------------------------------------
// Launcher — inputs: x, W_in, b_in, W_rec, b_rec, tau, num_layers
// ---------------------------------------------------------------------------
extern "C" void kernel_launch(void* const* d_in, const int* in_sizes, int n_in,
                              void* d_out, int out_size)
{
    const float* x    = (const float*)d_in[0];
    const float* Win  = (const float*)d_in[1];
    const float* bin  = (const float*)d_in[2];
    const float* Wrec = (const float*)d_in[3];
    const float* brec = (const float*)d_in[4];
    const float* tau  = (const float*)d_in[5];
    const int*   nl   = (n_in > 6) ? (const int*)d_in[6] : nullptr;

    const int H = in_sizes[2];              // 256
    const int I = in_sizes[1] / H;          // 128
    const int B = out_size / H;             // 64
    const int T = in_sizes[0] / (B * I);    // 4096
    const int M = B * T;

    float* xproj = nullptr;
    cudaGetSymbolAddress((void**)&xproj, g_xproj);

    dim3 grid1(H / XP_BN, M / XP_BM);
    xproj_kernel<<<grid1, 256>>>(x, Win, bin, xproj, M, I, H);

    // 2 batches per 2-CTA cluster: grid = 2 * ceil(B/2) CTAs
    const int nclusters = (B + 1) / 2;
    ltc_scan_kernel<<<2 * nclusters, LTC_H>>>(xproj, Wrec, brec, tau, nl,
                                              (float*)d_out, T, B);
}

// round 17
// speedup vs baseline: 1.5787x; 1.5787x over previous
#include <cuda_runtime.h>
#include <cstdint>
#include <cstddef>

// ---------------------------------------------------------------------------
// Scratch: x_proj buffer [B*T, H] = [262144, 256] fp32 = 256 MiB
// ---------------------------------------------------------------------------
__device__ float g_xproj[64u * 4096u * 256u];

// 2 * log2(e)
#define L2E2 2.8853900817779268f

// ---------------------------------------------------------------------------
// tanh on a PRE-SCALED argument z2 = 2*log2(e)*z :  tanh(z) = 1 - 2/(2^z2+1)
// ---------------------------------------------------------------------------
__device__ __forceinline__ float tanh_pre(float z2) {
    float e;
    asm("ex2.approx.f32 %0, %1;" : "=f"(e) : "f"(z2));
    float r;
    asm("rcp.approx.f32 %0, %1;" : "=f"(r) : "f"(e + 1.0f));
    return fmaf(-2.0f, r, 1.0f);
}

// ---------------------------------------------------------------------------
// Packed f32x2 helpers
// ---------------------------------------------------------------------------
__device__ __forceinline__ uint64_t ffma2(uint64_t a, uint64_t b, uint64_t c) {
    uint64_t d;
    asm("fma.rn.f32x2 %0, %1, %2, %3;" : "=l"(d) : "l"(a), "l"(b), "l"(c));
    return d;
}
__device__ __forceinline__ uint64_t fadd2(uint64_t a, uint64_t b) {
    uint64_t d;
    asm("add.rn.f32x2 %0, %1, %2;" : "=l"(d) : "l"(a), "l"(b));
    return d;
}
__device__ __forceinline__ float f2sum(uint64_t v) {
    float lo, hi;
    asm("mov.b64 {%0, %1}, %2;" : "=f"(lo), "=f"(hi) : "l"(v));
    return lo + hi;
}
__device__ __forceinline__ uint64_t pack2(float lo, float hi) {
    uint64_t d;
    asm("mov.b64 %0, {%1, %2};" : "=l"(d) : "f"(lo), "f"(hi));
    return d;
}
__device__ __forceinline__ void unpack2(uint64_t v, float& lo, float& hi) {
    asm("mov.b64 {%0, %1}, %2;" : "=f"(lo), "=f"(hi) : "l"(v));
}

__device__ __forceinline__ uint32_t smem_u32(const void* p) {
    uint32_t a;
    asm("{ .reg .u64 t; cvta.to.shared.u64 t, %1; cvt.u32.u64 %0, t; }"
        : "=r"(a) : "l"(p));
    return a;
}
__device__ __forceinline__ uint32_t mapa_rank(uint32_t laddr, uint32_t rank) {
    uint32_t raddr;
    asm("mapa.shared::cluster.u32 %0, %1, %2;" : "=r"(raddr) : "r"(laddr), "r"(rank));
    return raddr;
}
// Bulk smem->peer-smem copy; completes tx (bytes) on the given cluster-addr mbar.
__device__ __forceinline__ void bulk_s2s_cluster(uint32_t dst, uint32_t src,
                                                 uint32_t bytes, uint32_t rmbar) {
    asm volatile(
        "cp.async.bulk.shared::cluster.shared::cta.mbarrier::complete_tx::bytes "
        "[%0], [%1], %2, [%3];"
        :: "r"(dst), "r"(src), "r"(bytes), "r"(rmbar) : "memory");
}
__device__ __forceinline__ void mbar_init(uint32_t addr, uint32_t cnt) {
    asm volatile("mbarrier.init.shared.b64 [%0], %1;" :: "r"(addr), "r"(cnt) : "memory");
}
__device__ __forceinline__ void mbar_arrive_expect_tx(uint32_t addr, uint32_t tx) {
    asm volatile("mbarrier.arrive.expect_tx.shared.b64 _, [%0], %1;"
                 :: "r"(addr), "r"(tx) : "memory");
}
__device__ __forceinline__ void mbar_wait_parity(uint32_t addr, uint32_t parity) {
    uint32_t done;
    asm volatile(
        "{\n\t.reg .pred p;\n\t"
        "mbarrier.try_wait.parity.acquire.cta.shared::cta.b64 p, [%1], %2;\n\t"
        "selp.b32 %0, 1, 0, p;\n\t}"
        : "=r"(done) : "r"(addr), "r"(parity) : "memory");
    if (!done) {
        asm volatile(
            "{\n\t.reg .pred P1;\n\t"
            "WL_%=:\n\t"
            "mbarrier.try_wait.parity.acquire.cta.shared::cta.b64 P1, [%0], %1, 0x989680;\n\t"
            "@P1 bra.uni WD_%=;\n\t"
            "bra.uni WL_%=;\n\t"
            "WD_%=:\n\t}"
            :: "r"(addr), "r"(parity) : "memory");
    }
}

#define CLUSTER_SYNC_() do { \
    asm volatile("barrier.cluster.arrive.aligned;" ::: "memory"); \
    asm volatile("barrier.cluster.wait.aligned;" ::: "memory"); } while (0)

// ---------------------------------------------------------------------------
// Kernel 1: x_proj = x @ W_in^T + b_in  (128x128 tile, packed f32x2 FMA)
//   (unchanged from R12)
// ---------------------------------------------------------------------------
#define XP_BM 128
#define XP_BN 128
#define XP_BK 16

__global__ __launch_bounds__(256) void xproj_kernel(
    const float* __restrict__ x, const float* __restrict__ Win,
    const float* __restrict__ bin, float* __restrict__ out,
    int M, int K, int N)
{
    __shared__ float As[XP_BK][XP_BM];
    __shared__ float Bs[XP_BK][XP_BN];

    const int tid = threadIdx.x;
    const int tx = tid & 15;
    const int ty = tid >> 4;
    const int n0 = blockIdx.x * XP_BN;
    const int m0 = blockIdx.y * XP_BM;

    const int lr = tid >> 1;
    const int lc = (tid & 1) * 8;

    uint64_t cc[8][4];
    #pragma unroll
    for (int i = 0; i < 8; i++)
        #pragma unroll
        for (int jj = 0; jj < 4; jj++) cc[i][jj] = 0ull;

    for (int k0 = 0; k0 < K; k0 += XP_BK) {
        float4 xa0 = *(const float4*)(x   + (size_t)(m0 + lr) * K + k0 + lc);
        float4 xa1 = *(const float4*)(x   + (size_t)(m0 + lr) * K + k0 + lc + 4);
        float4 wb0 = *(const float4*)(Win + (size_t)(n0 + lr) * K + k0 + lc);
        float4 wb1 = *(const float4*)(Win + (size_t)(n0 + lr) * K + k0 + lc + 4);
        As[lc + 0][lr] = xa0.x; As[lc + 1][lr] = xa0.y;
        As[lc + 2][lr] = xa0.z; As[lc + 3][lr] = xa0.w;
        As[lc + 4][lr] = xa1.x; As[lc + 5][lr] = xa1.y;
        As[lc + 6][lr] = xa1.z; As[lc + 7][lr] = xa1.w;
        Bs[lc + 0][lr] = wb0.x; Bs[lc + 1][lr] = wb0.y;
        Bs[lc + 2][lr] = wb0.z; Bs[lc + 3][lr] = wb0.w;
        Bs[lc + 4][lr] = wb1.x; Bs[lc + 5][lr] = wb1.y;
        Bs[lc + 6][lr] = wb1.z; Bs[lc + 7][lr] = wb1.w;
        __syncthreads();

        #pragma unroll
        for (int kk = 0; kk < XP_BK; kk++) {
            float4 a0 = *(const float4*)(&As[kk][ty * 8]);
            float4 a1 = *(const float4*)(&As[kk][ty * 8 + 4]);
            ulonglong2 b0 = *(const ulonglong2*)(&Bs[kk][tx * 8]);
            ulonglong2 b1 = *(const ulonglong2*)(&Bs[kk][tx * 8 + 4]);
            float av[8] = {a0.x, a0.y, a0.z, a0.w, a1.x, a1.y, a1.z, a1.w};
            uint64_t bp[4] = {b0.x, b0.y, b1.x, b1.y};
            #pragma unroll
            for (int mi = 0; mi < 8; mi++) {
                uint64_t ap = pack2(av[mi], av[mi]);
                #pragma unroll
                for (int ni = 0; ni < 4; ni++)
                    cc[mi][ni] = ffma2(ap, bp[ni], cc[mi][ni]);
            }
        }
        __syncthreads();
    }

    float bb[8];
    #pragma unroll
    for (int ni = 0; ni < 8; ni++) bb[ni] = __ldg(&bin[n0 + tx * 8 + ni]);

    #pragma unroll
    for (int mi = 0; mi < 8; mi++) {
        int row = m0 + ty * 8 + mi;
        float c[8];
        #pragma unroll
        for (int ni = 0; ni < 4; ni++) unpack2(cc[mi][ni], c[2 * ni], c[2 * ni + 1]);
        float4 o0 = make_float4(c[0] + bb[0], c[1] + bb[1], c[2] + bb[2], c[3] + bb[3]);
        float4 o1 = make_float4(c[4] + bb[4], c[5] + bb[5], c[6] + bb[6], c[7] + bb[7]);
        *(float4*)(out + (size_t)row * N + n0 + tx * 8)     = o0;
        *(float4*)(out + (size_t)row * N + n0 + tx * 8 + 4) = o1;
    }
}

// ---------------------------------------------------------------------------
// Kernel 2: LTC scan — R12 champion + BULK single-copy partial exchange.
//   2-CTA cluster per batch, K-SPLIT: thread t owns output t, partial over
//   K-cols [rank*128,+128) with weights PRE-SCALED by 2*log2(e) (64 packed
//   f32x2 regs). Exchange: each thread STS's its partial into a contiguous
//   per-warp 128B staging chunk; after __syncwarp the warp-elect lane issues
//   fence.proxy.async + ONE cp.async.bulk (128B -> peer ppart chunk,
//   completing the peer mbar tx). 8 tx events/phase (was 128 st.async).
//   No shfl on the critical path; warps send as soon as they finish FMA.
//   Both CTAs finish tanh + h-update redundantly -> h stays CTA-local;
//   FMA never gated by a DSMEM arrival (partial-exchange invariant).
// ---------------------------------------------------------------------------
#define LTC_H 256

__global__ __launch_bounds__(256, 1) __cluster_dims__(2, 1, 1)
void ltc_scan_kernel(
    const float* __restrict__ xproj,
    const float* __restrict__ Wrec,
    const float* __restrict__ brec,
    const float* __restrict__ tau,
    const int*   __restrict__ nl_p,
    float* __restrict__ out, int T)
{
    __shared__ __align__(16) float hbuf[2][LTC_H];
    __shared__ __align__(16) float ppart[2][LTC_H];
    __shared__ __align__(16) float staging[2][LTC_H];
    __shared__ __align__(16) unsigned long long mbar[2];

    const int b = blockIdx.x >> 1;
    uint32_t rank;
    asm("mov.u32 %0, %%cluster_ctarank;" : "=r"(rank));
    const uint32_t peer = rank ^ 1u;

    const int t_ = threadIdx.x;              // output index 0..255
    const int wid = t_ >> 5;                 // warp id 0..7

    // --- W_rec[t][rank*128 .. +127] * 2log2e -> 64 packed f32x2 regs ------
    uint64_t wd[64];
    {
        const float4* wrow =
            (const float4*)(Wrec + (size_t)t_ * LTC_H + (rank << 7));
        #pragma unroll
        for (int i = 0; i < 32; i++) {
            float4 v = wrow[i];
            wd[2 * i]     = pack2(v.x * L2E2, v.y * L2E2);
            wd[2 * i + 1] = pack2(v.z * L2E2, v.w * L2E2);
        }
    }

    const float brec_j = brec[t_];
    const float scale_j = 0.1f / fminf(fmaxf(tau[t_], 0.1f), 5.0f);

    int NL = 2;
    if (nl_p) {
        int v = *nl_p;
        if (v >= 1 && v <= 64) NL = v;
    }

    const uint32_t mb[2] = { smem_u32(&mbar[0]), smem_u32(&mbar[1]) };
    if (t_ == 0) { mbar_init(mb[0], 1); mbar_init(mb[1], 1); }
    hbuf[0][t_] = 0.0f;
    hbuf[1][t_] = 0.0f;
    __syncthreads();
    CLUSTER_SYNC_();   // peer mbars + zeros visible before any bulk copy

    // per-warp staging chunk (local src) and peer ppart chunk (remote dst)
    const uint32_t src_st[2] = {
        smem_u32(&staging[0][wid * 32]),
        smem_u32(&staging[1][wid * 32])
    };
    const uint32_t r_pp[2] = {
        mapa_rank(smem_u32(&ppart[0][wid * 32]), peer),
        mapa_rank(smem_u32(&ppart[1][wid * 32]), peer)
    };
    const uint32_t r_mb[2] = { mapa_rank(mb[0], peer), mapa_rank(mb[1], peer) };

    const float* xrow = xproj + ((size_t)b * T) * LTC_H + t_;
    float xt = __ldg(xrow);                  // prefetch t = 0
    float hj = 0.0f;

    if (NL == 2) {
        for (int t = 0; t < T; t++) {
            const float base2 = (xt + brec_j) * L2E2;   // pre-scaled tanh arg
            if (t + 1 < T) xt = __ldg(xrow + (size_t)(t + 1) * LTC_H);
            const uint32_t par = (uint32_t)t & 1u;

            #pragma unroll
            for (int l = 0; l < 2; l++) {
                // arm this slot's phase (1 arrive + 8*128B = 1024B expected)
                if (t_ == 0) mbar_arrive_expect_tx(mb[l], LTC_H * 4u);

                // ---- partial dot product over my K-half (pre-scaled W) ----
                const ulonglong2* hp = (const ulonglong2*)(hbuf[l] + (rank << 7));
                uint64_t a0 = 0ull, a1 = 0ull, a2 = 0ull, a3 = 0ull;
                #pragma unroll
                for (int i = 0; i < 32; i += 2) {
                    ulonglong2 h0 = hp[i];
                    ulonglong2 h1 = hp[i + 1];
                    a0 = ffma2(wd[2 * i],     h0.x, a0);
                    a1 = ffma2(wd[2 * i + 1], h0.y, a1);
                    a2 = ffma2(wd[2 * i + 2], h1.x, a2);
                    a3 = ffma2(wd[2 * i + 3], h1.y, a3);
                }
                const float part = f2sum(fadd2(fadd2(a0, a1), fadd2(a2, a3)));

                // ---- stage + warp-elect bulk send (1 tx event per warp) ----
                staging[l][t_] = part;
                __syncwarp();
                if ((t_ & 31) == 0) {
                    asm volatile("fence.proxy.async.shared::cta;" ::: "memory");
                    bulk_s2s_cluster(r_pp[l], src_st[l], 128u, r_mb[l]);
                }

                // ---- wait for the peer's partials for this slot ----
                mbar_wait_parity(mb[l], par);

                // ---- finish output t_ redundantly ----
                const float act = tanh_pre(base2 + part + ppart[l][t_]);
                hj = fmaf(scale_j, act - hj, hj);

                hbuf[l ^ 1][t_] = hj;
                __syncthreads();
            }
        }
    } else {
        unsigned it = 0;
        uint32_t ph[2] = {0, 0};
        for (int t = 0; t < T; t++) {
            const float base2 = (xt + brec_j) * L2E2;
            if (t + 1 < T) xt = __ldg(xrow + (size_t)(t + 1) * LTC_H);
            for (int l = 0; l < NL; l++) {
                const int slot = it & 1u;
                if (t_ == 0) mbar_arrive_expect_tx(mb[slot], LTC_H * 4u);

                const ulonglong2* hp = (const ulonglong2*)(hbuf[slot] + (rank << 7));
                uint64_t a0 = 0ull, a1 = 0ull, a2 = 0ull, a3 = 0ull;
                #pragma unroll
                for (int i = 0; i < 32; i += 2) {
                    ulonglong2 h0 = hp[i];
                    ulonglong2 h1 = hp[i + 1];
                    a0 = ffma2(wd[2 * i],     h0.x, a0);
                    a1 = ffma2(wd[2 * i + 1], h0.y, a1);
                    a2 = ffma2(wd[2 * i + 2], h1.x, a2);
                    a3 = ffma2(wd[2 * i + 3], h1.y, a3);
                }
                const float part = f2sum(fadd2(fadd2(a0, a1), fadd2(a2, a3)));

                staging[slot][t_] = part;
                __syncwarp();
                if ((t_ & 31) == 0) {
                    asm volatile("fence.proxy.async.shared::cta;" ::: "memory");
                    bulk_s2s_cluster(r_pp[slot], src_st[slot], 128u, r_mb[slot]);
                }

                mbar_wait_parity(mb[slot], ph[slot]);
                ph[slot] ^= 1;

                const float act = tanh_pre(base2 + part + ppart[slot][t_]);
                hj = fmaf(scale_j, act - hj, hj);

                hbuf[slot ^ 1][t_] = hj;
                __syncthreads();
                it++;
            }
        }
    }

    if (rank == 0) out[(size_t)b * LTC_H + t_] = hj;

    CLUSTER_SYNC_();   // don't exit while peer bulk copies may target our smem
}

// ---------------------------------------------------------------------------
// Launcher — inputs: x, W_in, b_in, W_rec, b_rec, tau, num_layers
// ---------------------------------------------------------------------------
extern "C" void kernel_launch(void* const* d_in, const int* in_sizes, int n_in,
                              void* d_out, int out_size)
{
    const float* x    = (const float*)d_in[0];
    const float* Win  = (const float*)d_in[1];
    const float* bin  = (const float*)d_in[2];
    const float* Wrec = (const float*)d_in[3];
    const float* brec = (const float*)d_in[4];
    const float* tau  = (const float*)d_in[5];
    const int*   nl   = (n_in > 6) ? (const int*)d_in[6] : nullptr;

    const int H = in_sizes[2];              // 256
    const int I = in_sizes[1] / H;          // 128
    const int B = out_size / H;             // 64
    const int T = in_sizes[0] / (B * I);    // 4096
    const int M = B * T;

    float* xproj = nullptr;
    cudaGetSymbolAddress((void**)&xproj, g_xproj);

    dim3 grid1(H / XP_BN, M / XP_BM);
    xproj_kernel<<<grid1, 256>>>(x, Win, bin, xproj, M, I, H);

    ltc_scan_kernel<<<2 * B, LTC_H>>>(xproj, Wrec, brec, tau, nl,
                                      (float*)d_out, T);
}